// round 15
// baseline (speedup 1.0000x reference)
#include <cuda_runtime.h>
#include <cuda_bf16.h>
#include <cstdint>

#define BB  2
#define NN  1024
#define KK  48
#define HH  128
#define FFD 512
#define BN  (BB*NN)
#define NEDGE (BN*KK)          // 98304
#define MT  64
#define NCTA (NEDGE/MT)        // 1536
#define NTHR 256

// Three 32KB regions rotate roles. Tiles (SW128): B half = 16KB; A tile = 8KB.
#define TILE_W  16384
#define TILE_A  8192
#define REG0 1024
#define REG1 (REG0 + 32768)
#define REG2 (REG1 + 32768)
#define SM_TOTAL (REG2 + 32768)   // 99328 -> 2 CTAs/SM

#define WOFF_G1 0
#define WOFF_G2 (384*HH)
#define WOFF_G3 (WOFF_G2 + 128*HH)
#define WMSG    (WOFF_G3 + 128*HH)

__device__ float g_m[(size_t)NEDGE*HH];
__device__ float g_cw[BN*HH];
__device__ __align__(16) __nv_bfloat16 g_WThi[2*WMSG];
__device__ __align__(16) __nv_bfloat16 g_WTlo[2*WMSG];
__device__ __align__(16) __nv_bfloat16 g_hVhi[BN*HH],  g_hVlo[BN*HH];
__device__ __align__(16) __nv_bfloat16 g_hV2hi[BN*HH], g_hV2lo[BN*HH];
__device__ int g_idx64;

__device__ __forceinline__ float gelu_exact(float x) {
    return 0.5f * x * (1.0f + erff(x * 0.70710678118654752f));
}

__device__ __forceinline__ int load_nbidx(const void* Eidx, int is64, long long pos) {
    int v;
    if (is64) v = (int)((const long long*)Eidx)[pos];
    else      v = ((const int*)Eidx)[pos];
    v = v < 0 ? 0 : (v >= NN ? NN - 1 : v);
    return v;
}

// -------- prep: idx detect + 6 weight transposes + hV split + cw1 --------
#define PW_BLKS 640          // 163840 weight elements
#define PV_BLKS 256          // 65536 float4 of hV
#define PC_BLKS (BN/2)       // 1024 blocks, 2 nodes each (cw1)
__global__ void __launch_bounds__(256)
prep_all(const float* __restrict__ W1,  const float* __restrict__ W2,
         const float* __restrict__ W3,  const float* __restrict__ W11,
         const float* __restrict__ W12, const float* __restrict__ W13,
         const float* __restrict__ hV,  const float* __restrict__ W1b,
         const int* __restrict__ e32)
{
    __shared__ float sc[256];
    int blk = blockIdx.x, tid = threadIdx.x;
    if (blk == 0 && tid == 0) {
        int all0 = 1;
        #pragma unroll
        for (int i = 1; i < 96; i += 2) all0 &= (e32[i] == 0);
        g_idx64 = all0;
    }
    if (blk < PW_BLKS) {
        int id = blk * 256 + tid;
        const float* src; int base, K;
        if      (id < 49152)  { src = W1;  base = 0;      K = 384; }
        else if (id < 65536)  { src = W2;  base = 49152;  K = 128; }
        else if (id < 81920)  { src = W3;  base = 65536;  K = 128; }
        else if (id < 131072) { src = W11; base = 81920;  K = 384; }
        else if (id < 147456) { src = W12; base = 131072; K = 128; }
        else                  { src = W13; base = 147456; K = 128; }
        int local = id - base;
        int k = local >> 7, n = local & 127;
        float x = src[local];
        __nv_bfloat16 h = __float2bfloat16(x);
        g_WThi[base + (size_t)n * K + k] = h;
        g_WTlo[base + (size_t)n * K + k] = __float2bfloat16(x - __bfloat162float(h));
    } else if (blk < PW_BLKS + PV_BLKS) {
        int idx = (blk - PW_BLKS) * 256 + tid;
        float4 v = ((const float4*)hV)[idx];
        __nv_bfloat16 h0 = __float2bfloat16(v.x), h1 = __float2bfloat16(v.y);
        __nv_bfloat16 h2 = __float2bfloat16(v.z), h3 = __float2bfloat16(v.w);
        __nv_bfloat162* ph = (__nv_bfloat162*)(g_hVhi + (size_t)idx * 4);
        __nv_bfloat162* pl = (__nv_bfloat162*)(g_hVlo + (size_t)idx * 4);
        ph[0] = __nv_bfloat162(h0, h1); ph[1] = __nv_bfloat162(h2, h3);
        pl[0] = __nv_bfloat162(__float2bfloat16(v.x - __bfloat162float(h0)),
                               __float2bfloat16(v.y - __bfloat162float(h1)));
        pl[1] = __nv_bfloat162(__float2bfloat16(v.z - __bfloat162float(h2)),
                               __float2bfloat16(v.w - __bfloat162float(h3)));
    } else {
        // cw1: g_cw[bn][j] = W1b[j] + hV[bn,:] . W1[:128,j]   (2 nodes per block)
        int g = tid >> 7, j = tid & 127;
        int bn = (blk - PW_BLKS - PV_BLKS) * 2 + g;
        sc[g * 128 + j] = hV[(size_t)bn * HH + j];
        __syncthreads();
        float acc = W1b[j];
        const float* base = sc + g * 128;
        #pragma unroll 8
        for (int i = 0; i < 128; i++) acc = fmaf(base[i], W1[i * HH + j], acc);
        g_cw[(size_t)bn * HH + j] = acc;
    }
}

// ---------------- PTX helpers ----------------
__device__ __forceinline__ uint32_t smem_u32(const void* p) {
    uint32_t a;
    asm("{ .reg .u64 t; cvta.to.shared.u64 t, %1; cvt.u32.u64 %0, t; }" : "=r"(a) : "l"(p));
    return a;
}
__device__ __forceinline__ uint32_t sw128(uint32_t off) {
    return off ^ ((off >> 3) & 0x70);
}
__device__ __forceinline__ void cp_async16(uint32_t dst, const void* src) {
    asm volatile("cp.async.cg.shared.global [%0], [%1], 16;" :: "r"(dst), "l"(src));
}
#define CP_WAIT_ALL() asm volatile("cp.async.wait_all;" ::: "memory")
__device__ __forceinline__ void ldsm4(uint32_t* r, uint32_t addr) {
    asm volatile("ldmatrix.sync.aligned.m8n8.x4.shared.b16 {%0,%1,%2,%3}, [%4];"
        : "=r"(r[0]), "=r"(r[1]), "=r"(r[2]), "=r"(r[3]) : "r"(addr));
}
__device__ __forceinline__ void mma16816(float* d, const uint32_t* a, const uint32_t* b) {
    asm volatile("mma.sync.aligned.m16n8k16.row.col.f32.bf16.bf16.f32 "
        "{%0,%1,%2,%3}, {%4,%5,%6,%7}, {%8,%9}, {%0,%1,%2,%3};"
        : "+f"(d[0]), "+f"(d[1]), "+f"(d[2]), "+f"(d[3])
        : "r"(a[0]), "r"(a[1]), "r"(a[2]), "r"(a[3]), "r"(b[0]), "r"(b[1]));
}
__device__ __forceinline__ void ldsmA(uint32_t* r, uint32_t tbase, int mrow, int klo, int lane) {
    int q = lane >> 3;
    int row = mrow + (lane & 7) + 8 * (q & 1);
    int kk  = klo + 8 * (q >> 1);
    ldsm4(r, tbase + sw128((uint32_t)(row * 128 + kk * 2)));
}
__device__ __forceinline__ void ldsmB(uint32_t* r, uint32_t tbase, int nrow0, int klo, int lane) {
    int q = lane >> 3;
    int row = nrow0 + (lane & 7) + 8 * (q >> 1);
    int kk  = klo + 8 * (q & 1);
    ldsm4(r, tbase + sw128((uint32_t)(row * 128 + kk * 2)));
}
__device__ __forceinline__ uint32_t pack_bf2(__nv_bfloat16 a, __nv_bfloat16 b) {
    return (uint32_t)__bfloat16_as_ushort(a) | ((uint32_t)__bfloat16_as_ushort(b) << 16);
}
__device__ __forceinline__ void split2(float x, float y, uint32_t& hi, uint32_t& lo) {
    __nv_bfloat16 hx = __float2bfloat16(x), hy = __float2bfloat16(y);
    __nv_bfloat16 lx = __float2bfloat16(x - __bfloat162float(hx));
    __nv_bfloat16 ly = __float2bfloat16(y - __bfloat162float(hy));
    hi = pack_bf2(hx, hy);
    lo = pack_bf2(lx, ly);
}

// warp tile 32(m) x 32(n): acc[2][4][4]; per k16: 8 LDSM vs 24 HMMA
__device__ __forceinline__ void mma_chunk(uint32_t aHi, uint32_t aLo,
                                          uint32_t bHi, uint32_t bLo,
                                          int m0, int n0, int lane,
                                          float acc[2][4][4]) {
    #pragma unroll
    for (int ks = 0; ks < 4; ks++) {
        int klo = ks * 16;
        uint32_t Ah[2][4], Al[2][4];
        #pragma unroll
        for (int mt = 0; mt < 2; mt++) {
            ldsmA(Ah[mt], aHi, m0 + 16 * mt, klo, lane);
            ldsmA(Al[mt], aLo, m0 + 16 * mt, klo, lane);
        }
        uint32_t Bh[2][4], Bl[2][4];
        #pragma unroll
        for (int p = 0; p < 2; p++) {
            ldsmB(Bh[p], bHi, n0 + p * 16, klo, lane);
            ldsmB(Bl[p], bLo, n0 + p * 16, klo, lane);
        }
        #pragma unroll
        for (int mt = 0; mt < 2; mt++) {
            #pragma unroll
            for (int p = 0; p < 2; p++) {
                #pragma unroll
                for (int s = 0; s < 2; s++) {
                    int nt = p * 2 + s;
                    mma16816(acc[mt][nt], Ah[mt], &Bh[p][s * 2]);
                    mma16816(acc[mt][nt], Ah[mt], &Bl[p][s * 2]);
                    mma16816(acc[mt][nt], Al[mt], &Bh[p][s * 2]);
                }
            }
        }
    }
}

// ---------------- fused GEMM-chain message kernel (unchanged from R14) ----------------
template<bool EDGE>
__global__ void __launch_bounds__(NTHR, 2)
gemm_msg_kernel(const __nv_bfloat16* __restrict__ vhi,
                const __nv_bfloat16* __restrict__ vlo,
                const float* __restrict__ hE,
                const void*  __restrict__ Eidx,
                const float* __restrict__ maskA,
                const float* __restrict__ bb, const float* __restrict__ bc,
                int wbase,
                const float* __restrict__ lng, const float* __restrict__ lnb,
                float* __restrict__ out)
{
    extern __shared__ uint8_t smem8[];
    const int tid  = threadIdx.x;
    const int wid  = tid >> 5;
    const int lane = tid & 31;
    const int e0   = blockIdx.x * MT;
    const int is64 = g_idx64;
    const uint32_t sbase = smem_u32(smem8);

    const int m0 = (wid & 1) * 32;
    const int n0 = (wid >> 1) * 32;

    const __nv_bfloat16* WTh = g_WThi + wbase;
    const __nv_bfloat16* WTl = g_WTlo + wbase;

    float acc[2][4][4];
    auto zero_acc = [&]() {
        #pragma unroll
        for (int mt = 0; mt < 2; mt++)
            #pragma unroll
            for (int nt = 0; nt < 4; nt++)
                #pragma unroll
                for (int i = 0; i < 4; i++) acc[mt][nt][i] = 0.f;
    };

    auto fill_B = [&](int woff, int Klen, int kbase, uint32_t reg) {
        const __nv_bfloat16* bh = WTh + woff;
        const __nv_bfloat16* bl = WTl + woff;
        int u = tid & 7;
        #pragma unroll
        for (int n = tid >> 3; n < 128; n += 32) {
            uint32_t sw = sw128((uint32_t)n * 128 + u * 16);
            cp_async16(sbase + reg + sw,          bh + (size_t)n * Klen + kbase + u * 8);
            cp_async16(sbase + reg + TILE_W + sw, bl + (size_t)n * Klen + kbase + u * 8);
        }
    };

    auto fill_A = [&](int ch, int slot) {
        uint32_t aH = sbase + REG2 + slot * TILE_A;
        uint32_t aL = aH + 2 * TILE_A;
        if (ch < 2) {
            uint8_t* pH = smem8 + REG2 + slot * TILE_A;
            uint8_t* pL = pH + 2 * TILE_A;
            int c4 = tid & 15;
            #pragma unroll
            for (int r = tid >> 4; r < MT; r += 16) {
                int e = e0 + r;
                const float* src = hE + (size_t)e * HH + ch * 64;
                float4 v = *((const float4*)src + c4);
                uint32_t h01, l01, h23, l23;
                split2(v.x, v.y, h01, l01);
                split2(v.z, v.w, h23, l23);
                uint32_t sw = sw128((uint32_t)r * 128 + c4 * 8);
                *(uint2*)(pH + sw) = make_uint2(h01, h23);
                *(uint2*)(pL + sw) = make_uint2(l01, l23);
            }
        } else {
            int u = tid & 7;
            #pragma unroll
            for (int r = tid >> 3; r < MT; r += 32) {
                int e = e0 + r;
                int b  = e / (KK * NN);
                int nb = load_nbidx(Eidx, is64, e);
                size_t off = ((size_t)b * NN + nb) * HH + (ch - 2) * 64 + u * 8;
                uint32_t sw = sw128((uint32_t)r * 128 + u * 16);
                cp_async16(aH + sw, vhi + off);
                cp_async16(aL + sw, vlo + off);
            }
        }
    };

    auto epi_act = [&](const float* __restrict__ bias, bool useCW, uint32_t dstReg) {
        #pragma unroll
        for (int mt = 0; mt < 2; mt++) {
            int row = m0 + mt * 16 + (lane >> 2);
            const float* cw0 = nullptr; const float* cw1 = nullptr;
            if (useCW) {
                cw0 = g_cw + (size_t)((e0 + row) / KK) * HH;
                cw1 = g_cw + (size_t)((e0 + row + 8) / KK) * HH;
            }
            #pragma unroll
            for (int nt = 0; nt < 4; nt++) {
                int c0 = n0 + nt * 8 + 2 * (lane & 3);
                float b00, b01, b10, b11;
                if (useCW) { b00 = cw0[c0]; b01 = cw0[c0 + 1]; b10 = cw1[c0]; b11 = cw1[c0 + 1]; }
                else       { b00 = b10 = bias[c0]; b01 = b11 = bias[c0 + 1]; }
                int kc = c0 >> 6, kk = c0 & 63;
                uint8_t* dH = smem8 + dstReg + kc * TILE_A;
                uint8_t* dL = dH + 2 * TILE_A;
                float x0 = gelu_exact(acc[mt][nt][0] + b00);
                float y0 = gelu_exact(acc[mt][nt][1] + b01);
                float x1 = gelu_exact(acc[mt][nt][2] + b10);
                float y1 = gelu_exact(acc[mt][nt][3] + b11);
                uint32_t hi, lo;
                split2(x0, y0, hi, lo);
                uint32_t sw = sw128((uint32_t)(row * 128 + kk * 2));
                *(uint32_t*)(dH + sw) = hi; *(uint32_t*)(dL + sw) = lo;
                split2(x1, y1, hi, lo);
                sw = sw128((uint32_t)((row + 8) * 128 + kk * 2));
                *(uint32_t*)(dH + sw) = hi; *(uint32_t*)(dL + sw) = lo;
            }
        }
    };

    auto mmaA = [&](uint32_t reg, int kc, uint32_t bReg) {
        mma_chunk(sbase + reg + kc * TILE_A, sbase + reg + 2 * TILE_A + kc * TILE_A,
                  sbase + bReg, sbase + bReg + TILE_W, m0, n0, lane, acc);
    };

    // ===== GEMM1: K=256, 4 chunks. A ping-pong in R2, B ping-pong R0/R1 =====
    zero_acc();
    fill_B(WOFF_G1, 384, 128, REG0);
    fill_A(0, 0);
    CP_WAIT_ALL();
    __syncthreads();
    fill_A(1, 1); fill_B(WOFF_G1, 384, 192, REG1);
    mmaA(REG2, 0, REG0);
    CP_WAIT_ALL(); __syncthreads();
    fill_A(2, 0); fill_B(WOFF_G1, 384, 256, REG0);
    mmaA(REG2, 1, REG1);
    CP_WAIT_ALL(); __syncthreads();
    fill_A(3, 1); fill_B(WOFF_G1, 384, 320, REG1);
    mmaA(REG2, 0, REG0);
    CP_WAIT_ALL(); __syncthreads();
    mmaA(REG2, 1, REG1);
    __syncthreads();

    // ===== epilogue1 (+cw) -> R2; B(G2,k0) -> R0 =====
    fill_B(WOFF_G2, 128, 0, REG0);
    epi_act(nullptr, true, REG2);
    zero_acc();
    CP_WAIT_ALL(); __syncthreads();

    // ===== GEMM2: A in R2, B R0 then R1 =====
    fill_B(WOFF_G2, 128, 64, REG1);
    mmaA(REG2, 0, REG0);
    CP_WAIT_ALL(); __syncthreads();
    fill_B(WOFF_G3, 128, 0, REG0);
    mmaA(REG2, 1, REG1);
    CP_WAIT_ALL(); __syncthreads();

    // ===== epilogue2 -> R1; B(G3,k64) -> R2 =====
    fill_B(WOFF_G3, 128, 64, REG2);
    epi_act(bb, false, REG1);
    zero_acc();
    CP_WAIT_ALL(); __syncthreads();

    // ===== GEMM3: A in R1, B R0 then R2 =====
    mmaA(REG1, 0, REG0);
    mmaA(REG1, 1, REG2);
    __syncthreads();

    float* sOut = (float*)(smem8 + REG0);
    {
        #pragma unroll
        for (int mt = 0; mt < 2; mt++) {
            int row = m0 + mt * 16 + (lane >> 2);
            float mk0 = 1.f, mk1 = 1.f;
            if (!EDGE) { mk0 = maskA[e0 + row]; mk1 = maskA[e0 + row + 8]; }
            #pragma unroll
            for (int nt = 0; nt < 4; nt++) {
                int c0 = n0 + nt * 8 + 2 * (lane & 3);
                float b0v = bc[c0], b1v = bc[c0 + 1];
                sOut[row * 128 + c0]           = (acc[mt][nt][0] + b0v) * mk0;
                sOut[row * 128 + c0 + 1]       = (acc[mt][nt][1] + b1v) * mk0;
                sOut[(row + 8) * 128 + c0]     = (acc[mt][nt][2] + b0v) * mk1;
                sOut[(row + 8) * 128 + c0 + 1] = (acc[mt][nt][3] + b1v) * mk1;
            }
        }
        __syncthreads();
    }

    if (!EDGE) {
        float4* d4 = (float4*)(g_m + (size_t)e0 * HH);
        const float4* s4 = (const float4*)sOut;
        #pragma unroll
        for (int p = 0; p < 8; p++) d4[tid + p * NTHR] = s4[tid + p * NTHR];
    } else {
        for (int r = wid; r < MT; r += 8) {
            const float* her = hE + (size_t)(e0 + r) * HH;
            float v[4];
            #pragma unroll
            for (int u = 0; u < 4; u++) {
                int c = lane + 32 * u;
                v[u] = sOut[r * 128 + c] + her[c];
            }
            float s  = v[0] + v[1] + v[2] + v[3];
            float ss = v[0]*v[0] + v[1]*v[1] + v[2]*v[2] + v[3]*v[3];
            #pragma unroll
            for (int o = 16; o; o >>= 1) {
                s  += __shfl_xor_sync(0xffffffffu, s, o);
                ss += __shfl_xor_sync(0xffffffffu, ss, o);
            }
            float mean = s * (1.0f / 128.0f);
            float rstd = rsqrtf(ss * (1.0f / 128.0f) - mean * mean + 1e-5f);
            #pragma unroll
            for (int u = 0; u < 4; u++) {
                int c = lane + 32 * u;
                out[(size_t)(e0 + r) * HH + c] = (v[u] - mean) * rstd * lng[c] + lnb[c];
            }
        }
    }
}

// ---------------- mega FFN: LN1-reduce + FFN + LN2 + mask + h_Vn split + cw2 ----------------
__global__ void __launch_bounds__(256, 1)
ffn_kernel(const float* __restrict__ hVin,
           const float* __restrict__ ln1g, const float* __restrict__ ln1b,
           const float* __restrict__ Win, const float* __restrict__ bin,
           const float* __restrict__ Wout, const float* __restrict__ bout,
           const float* __restrict__ lng, const float* __restrict__ lnb,
           const float* __restrict__ maskV,
           const float* __restrict__ W11, const float* __restrict__ W11b,
           float* __restrict__ out)
{
    __shared__ float sX[16 * 128];
    __shared__ float sH[16 * 512];
    __shared__ float rs[2][4], rq[2][4];
    const int tid  = threadIdx.x;
    const int row0 = blockIdx.x * 16;
    const int lane = tid & 31;

    // ---- phase 0: reduce g_m over K + residual + LN1 -> sX ----
    {
        int grp = tid >> 7;            // two 128-thread row groups
        int j   = tid & 127;
        int w4  = (tid >> 5) & 3;
        for (int rr = grp; rr < 16; rr += 2) {
            int bn = row0 + rr;
            const float* mp = g_m + (size_t)bn * KK * HH + j;
            float s = 0.f;
            #pragma unroll 8
            for (int k = 0; k < KK; k++) s += mp[(size_t)k * HH];
            float v = hVin[(size_t)bn * HH + j] + s * (1.0f / 48.0f);
            float a = v, q = v * v;
            #pragma unroll
            for (int o = 16; o; o >>= 1) {
                a += __shfl_xor_sync(0xffffffffu, a, o);
                q += __shfl_xor_sync(0xffffffffu, q, o);
            }
            if (lane == 0) { rs[grp][w4] = a; rq[grp][w4] = q; }
            __syncthreads();
            float S = rs[grp][0] + rs[grp][1] + rs[grp][2] + rs[grp][3];
            float Q = rq[grp][0] + rq[grp][1] + rq[grp][2] + rq[grp][3];
            float mean = S * (1.0f / 128.0f);
            float rstd = rsqrtf(Q * (1.0f / 128.0f) - mean * mean + 1e-5f);
            sX[rr * 128 + j] = (v - mean) * rstd * ln1g[j] + ln1b[j];
            __syncthreads();
        }
    }

    // ---- phase 1: hidden ----
    {
        const int j0 = tid * 2;
        float acc[16][2];
        #pragma unroll
        for (int r = 0; r < 16; r++) { acc[r][0] = bin[j0]; acc[r][1] = bin[j0 + 1]; }
        #pragma unroll 2
        for (int i = 0; i < 128; i++) {
            float2 w = *reinterpret_cast<const float2*>(Win + i * FFD + j0);
            #pragma unroll
            for (int r = 0; r < 16; r++) {
                float a = sX[r * 128 + i];
                acc[r][0] = fmaf(a, w.x, acc[r][0]);
                acc[r][1] = fmaf(a, w.y, acc[r][1]);
            }
        }
        #pragma unroll
        for (int r = 0; r < 16; r++) {
            sH[r * FFD + j0]     = gelu_exact(acc[r][0]);
            sH[r * FFD + j0 + 1] = gelu_exact(acc[r][1]);
        }
    }
    __syncthreads();

    // ---- phase 2: output projection + residual ----
    {
        const int j = tid & 127, rh = tid >> 7;
        float acc[8];
        #pragma unroll
        for (int r = 0; r < 8; r++) acc[r] = bout[j];
        #pragma unroll 2
        for (int i = 0; i < FFD; i++) {
            float w = Wout[i * 128 + j];
            #pragma unroll
            for (int r = 0; r < 8; r++)
                acc[r] = fmaf(sH[(rh * 8 + r) * FFD + i], w, acc[r]);
        }
        #pragma unroll
        for (int r = 0; r < 8; r++)
            sX[(rh * 8 + r) * 128 + j] += acc[r];
    }
    __syncthreads();

    // ---- phase 3: LN2 + mask -> out + bf16 split; stash h_Vn into sH ----
    {
        int w = tid >> 5;
        for (int r = w; r < 16; r += 8) {
            float v[4];
            #pragma unroll
            for (int u = 0; u < 4; u++) v[u] = sX[r * 128 + lane + 32 * u];
            float s  = v[0] + v[1] + v[2] + v[3];
            float ss = v[0]*v[0] + v[1]*v[1] + v[2]*v[2] + v[3]*v[3];
            #pragma unroll
            for (int o = 16; o; o >>= 1) {
                s  += __shfl_xor_sync(0xffffffffu, s, o);
                ss += __shfl_xor_sync(0xffffffffu, ss, o);
            }
            float mean = s * (1.0f / 128.0f);
            float rstd = rsqrtf(ss * (1.0f / 128.0f) - mean * mean + 1e-5f);
            float mk = maskV[row0 + r];
            #pragma unroll
            for (int u = 0; u < 4; u++) {
                int c = lane + 32 * u;
                float val = mk * ((v[u] - mean) * rstd * lng[c] + lnb[c]);
                size_t gi = ((size_t)row0 + r) * 128 + c;
                out[gi] = val;
                __nv_bfloat16 h = __float2bfloat16(val);
                g_hV2hi[gi] = h;
                g_hV2lo[gi] = __float2bfloat16(val - __bfloat162float(h));
                sH[r * 128 + c] = val;
            }
        }
    }
    __syncthreads();

    // ---- phase 4: cw2[row][j] = W11b[j] + h_Vn . W11[:128,j] ----
    {
        int g = tid >> 7, j = tid & 127;
        float acc[8];
        #pragma unroll
        for (int r8 = 0; r8 < 8; r8++) acc[r8] = W11b[j];
        #pragma unroll 4
        for (int i = 0; i < 128; i++) {
            float w = W11[i * HH + j];
            #pragma unroll
            for (int r8 = 0; r8 < 8; r8++)
                acc[r8] = fmaf(sH[(g + 2 * r8) * 128 + i], w, acc[r8]);
        }
        #pragma unroll
        for (int r8 = 0; r8 < 8; r8++)
            g_cw[(size_t)(row0 + g + 2 * r8) * HH + j] = acc[r8];
    }
}

extern "C" void kernel_launch(void* const* d_in, const int* in_sizes, int n_in,
                              void* d_out, int out_size)
{
    const float* hV    = (const float*)d_in[0];
    const float* hE    = (const float*)d_in[1];
    const void*  Eidx  = d_in[2];
    const float* maskV = (const float*)d_in[3];
    const float* maskA = (const float*)d_in[4];
    const float* W1w  = (const float*)d_in[5],  *W1b  = (const float*)d_in[6];
    const float* W2w  = (const float*)d_in[7],  *W2b  = (const float*)d_in[8];
    const float* W3w  = (const float*)d_in[9],  *W3b  = (const float*)d_in[10];
    const float* W11w = (const float*)d_in[11], *W11b = (const float*)d_in[12];
    const float* W12w = (const float*)d_in[13], *W12b = (const float*)d_in[14];
    const float* W13w = (const float*)d_in[15], *W13b = (const float*)d_in[16];
    const float* Winw = (const float*)d_in[17], *Winb = (const float*)d_in[18];
    const float* Woutw= (const float*)d_in[19], *Woutb= (const float*)d_in[20];
    const float* ln1g = (const float*)d_in[21], *ln1b = (const float*)d_in[22];
    const float* ln2g = (const float*)d_in[23], *ln2b = (const float*)d_in[24];
    const float* ln3g = (const float*)d_in[25], *ln3b = (const float*)d_in[26];

    float* out_hV = (float*)d_out;
    float* out_hE = out_hV + (size_t)BN * HH;

    cudaFuncSetAttribute(gemm_msg_kernel<false>, cudaFuncAttributeMaxDynamicSharedMemorySize, SM_TOTAL);
    cudaFuncSetAttribute(gemm_msg_kernel<true>,  cudaFuncAttributeMaxDynamicSharedMemorySize, SM_TOTAL);

    __nv_bfloat16 *vhi, *vlo, *v2hi, *v2lo;
    cudaGetSymbolAddress((void**)&vhi,  g_hVhi);
    cudaGetSymbolAddress((void**)&vlo,  g_hVlo);
    cudaGetSymbolAddress((void**)&v2hi, g_hV2hi);
    cudaGetSymbolAddress((void**)&v2lo, g_hV2lo);

    // 1) prep: idx detect + weight transposes + hV split + cw1
    prep_all<<<PW_BLKS + PV_BLKS + PC_BLKS, 256>>>(
        W1w, W2w, W3w, W11w, W12w, W13w, hV, W1b, (const int*)Eidx);
    // 2) node message chain -> g_m
    gemm_msg_kernel<false><<<NCTA, NTHR, SM_TOTAL>>>(
        vhi, vlo, hE, Eidx, maskA, W2b, W3b, 0, nullptr, nullptr, nullptr);
    // 3) LN1 + FFN + LN2 + mask + split + cw2
    ffn_kernel<<<BN / 16, 256>>>(hV, ln1g, ln1b, Winw, Winb, Woutw, Woutb,
                                 ln2g, ln2b, maskV, W11w, W11b, out_hV);
    // 4) edge message chain + LN3
    gemm_msg_kernel<true><<<NCTA, NTHR, SM_TOTAL>>>(
        v2hi, v2lo, hE, Eidx, maskA, W12b, W13b, WMSG, ln3g, ln3b, out_hE);

    (void)in_sizes; (void)n_in; (void)out_size;
}

// round 16
// speedup vs baseline: 1.0002x; 1.0002x over previous
#include <cuda_runtime.h>
#include <cuda_bf16.h>
#include <cstdint>

#define BB  2
#define NN  1024
#define KK  48
#define HH  128
#define FFD 512
#define BN  (BB*NN)
#define NEDGE (BN*KK)          // 98304
#define MT  64
#define NCTA (NEDGE/MT)        // 1536
#define NTHR 256

// Three 32KB regions rotate roles. Tiles (SW128): B half = 16KB; A tile = 8KB.
#define TILE_W  16384
#define TILE_A  8192
#define REG0 1024
#define REG1 (REG0 + 32768)
#define REG2 (REG1 + 32768)
#define SM_TOTAL (REG2 + 32768)   // 99328 -> 2 CTAs/SM

#define WOFF_G1 0
#define WOFF_G2 (384*HH)
#define WOFF_G3 (WOFF_G2 + 128*HH)
#define WMSG    (WOFF_G3 + 128*HH)

__device__ float g_hV1[BN*HH];
__device__ float g_m[(size_t)NEDGE*HH];
__device__ float g_cw[BN*HH];
__device__ __align__(16) __nv_bfloat16 g_WThi[2*WMSG];
__device__ __align__(16) __nv_bfloat16 g_WTlo[2*WMSG];
__device__ __align__(16) __nv_bfloat16 g_hVhi[BN*HH],  g_hVlo[BN*HH];
__device__ __align__(16) __nv_bfloat16 g_hV2hi[BN*HH], g_hV2lo[BN*HH];
__device__ int g_idx64;

__device__ __forceinline__ float gelu_exact(float x) {
    return 0.5f * x * (1.0f + erff(x * 0.70710678118654752f));
}

__device__ __forceinline__ int load_nbidx(const void* Eidx, int is64, long long pos) {
    int v;
    if (is64) v = (int)((const long long*)Eidx)[pos];
    else      v = ((const int*)Eidx)[pos];
    v = v < 0 ? 0 : (v >= NN ? NN - 1 : v);
    return v;
}

// -------- prep: idx detect + 6 weight transposes + hV split + cw1 --------
#define PW_BLKS 640          // 163840 weight elements
#define PV_BLKS 256          // 65536 float4 of hV
#define PC_BLKS (BN/2)       // 1024 blocks, 2 nodes each (cw1)
__global__ void __launch_bounds__(256)
prep_all(const float* __restrict__ W1,  const float* __restrict__ W2,
         const float* __restrict__ W3,  const float* __restrict__ W11,
         const float* __restrict__ W12, const float* __restrict__ W13,
         const float* __restrict__ hV,  const float* __restrict__ W1b,
         const int* __restrict__ e32)
{
    __shared__ float sc[256];
    int blk = blockIdx.x, tid = threadIdx.x;
    if (blk == 0 && tid == 0) {
        int all0 = 1;
        #pragma unroll
        for (int i = 1; i < 96; i += 2) all0 &= (e32[i] == 0);
        g_idx64 = all0;
    }
    if (blk < PW_BLKS) {
        int id = blk * 256 + tid;
        const float* src; int base, K;
        if      (id < 49152)  { src = W1;  base = 0;      K = 384; }
        else if (id < 65536)  { src = W2;  base = 49152;  K = 128; }
        else if (id < 81920)  { src = W3;  base = 65536;  K = 128; }
        else if (id < 131072) { src = W11; base = 81920;  K = 384; }
        else if (id < 147456) { src = W12; base = 131072; K = 128; }
        else                  { src = W13; base = 147456; K = 128; }
        int local = id - base;
        int k = local >> 7, n = local & 127;
        float x = src[local];
        __nv_bfloat16 h = __float2bfloat16(x);
        g_WThi[base + (size_t)n * K + k] = h;
        g_WTlo[base + (size_t)n * K + k] = __float2bfloat16(x - __bfloat162float(h));
    } else if (blk < PW_BLKS + PV_BLKS) {
        int idx = (blk - PW_BLKS) * 256 + tid;
        float4 v = ((const float4*)hV)[idx];
        __nv_bfloat16 h0 = __float2bfloat16(v.x), h1 = __float2bfloat16(v.y);
        __nv_bfloat16 h2 = __float2bfloat16(v.z), h3 = __float2bfloat16(v.w);
        __nv_bfloat162* ph = (__nv_bfloat162*)(g_hVhi + (size_t)idx * 4);
        __nv_bfloat162* pl = (__nv_bfloat162*)(g_hVlo + (size_t)idx * 4);
        ph[0] = __nv_bfloat162(h0, h1); ph[1] = __nv_bfloat162(h2, h3);
        pl[0] = __nv_bfloat162(__float2bfloat16(v.x - __bfloat162float(h0)),
                               __float2bfloat16(v.y - __bfloat162float(h1)));
        pl[1] = __nv_bfloat162(__float2bfloat16(v.z - __bfloat162float(h2)),
                               __float2bfloat16(v.w - __bfloat162float(h3)));
    } else {
        // cw1: g_cw[bn][j] = W1b[j] + hV[bn,:] . W1[:128,j]   (2 nodes per block)
        int g = tid >> 7, j = tid & 127;
        int bn = (blk - PW_BLKS - PV_BLKS) * 2 + g;
        sc[g * 128 + j] = hV[(size_t)bn * HH + j];
        __syncthreads();
        float acc = W1b[j];
        const float* base = sc + g * 128;
        #pragma unroll 8
        for (int i = 0; i < 128; i++) acc = fmaf(base[i], W1[i * HH + j], acc);
        g_cw[(size_t)bn * HH + j] = acc;
    }
}

// ---------------- PTX helpers ----------------
__device__ __forceinline__ uint32_t smem_u32(const void* p) {
    uint32_t a;
    asm("{ .reg .u64 t; cvta.to.shared.u64 t, %1; cvt.u32.u64 %0, t; }" : "=r"(a) : "l"(p));
    return a;
}
__device__ __forceinline__ uint32_t sw128(uint32_t off) {
    return off ^ ((off >> 3) & 0x70);
}
__device__ __forceinline__ void cp_async16(uint32_t dst, const void* src) {
    asm volatile("cp.async.cg.shared.global [%0], [%1], 16;" :: "r"(dst), "l"(src));
}
#define CP_WAIT_ALL() asm volatile("cp.async.wait_all;" ::: "memory")
__device__ __forceinline__ void ldsm4(uint32_t* r, uint32_t addr) {
    asm volatile("ldmatrix.sync.aligned.m8n8.x4.shared.b16 {%0,%1,%2,%3}, [%4];"
        : "=r"(r[0]), "=r"(r[1]), "=r"(r[2]), "=r"(r[3]) : "r"(addr));
}
__device__ __forceinline__ void mma16816(float* d, const uint32_t* a, const uint32_t* b) {
    asm volatile("mma.sync.aligned.m16n8k16.row.col.f32.bf16.bf16.f32 "
        "{%0,%1,%2,%3}, {%4,%5,%6,%7}, {%8,%9}, {%0,%1,%2,%3};"
        : "+f"(d[0]), "+f"(d[1]), "+f"(d[2]), "+f"(d[3])
        : "r"(a[0]), "r"(a[1]), "r"(a[2]), "r"(a[3]), "r"(b[0]), "r"(b[1]));
}
__device__ __forceinline__ void ldsmA(uint32_t* r, uint32_t tbase, int mrow, int klo, int lane) {
    int q = lane >> 3;
    int row = mrow + (lane & 7) + 8 * (q & 1);
    int kk  = klo + 8 * (q >> 1);
    ldsm4(r, tbase + sw128((uint32_t)(row * 128 + kk * 2)));
}
__device__ __forceinline__ void ldsmB(uint32_t* r, uint32_t tbase, int nrow0, int klo, int lane) {
    int q = lane >> 3;
    int row = nrow0 + (lane & 7) + 8 * (q >> 1);
    int kk  = klo + 8 * (q & 1);
    ldsm4(r, tbase + sw128((uint32_t)(row * 128 + kk * 2)));
}
__device__ __forceinline__ uint32_t pack_bf2(__nv_bfloat16 a, __nv_bfloat16 b) {
    return (uint32_t)__bfloat16_as_ushort(a) | ((uint32_t)__bfloat16_as_ushort(b) << 16);
}
__device__ __forceinline__ void split2(float x, float y, uint32_t& hi, uint32_t& lo) {
    __nv_bfloat16 hx = __float2bfloat16(x), hy = __float2bfloat16(y);
    __nv_bfloat16 lx = __float2bfloat16(x - __bfloat162float(hx));
    __nv_bfloat16 ly = __float2bfloat16(y - __bfloat162float(hy));
    hi = pack_bf2(hx, hy);
    lo = pack_bf2(lx, ly);
}

// warp tile 32(m) x 32(n): acc[2][4][4]; per k16: 8 LDSM vs 24 HMMA
__device__ __forceinline__ void mma_chunk(uint32_t aHi, uint32_t aLo,
                                          uint32_t bHi, uint32_t bLo,
                                          int m0, int n0, int lane,
                                          float acc[2][4][4]) {
    #pragma unroll
    for (int ks = 0; ks < 4; ks++) {
        int klo = ks * 16;
        uint32_t Ah[2][4], Al[2][4];
        #pragma unroll
        for (int mt = 0; mt < 2; mt++) {
            ldsmA(Ah[mt], aHi, m0 + 16 * mt, klo, lane);
            ldsmA(Al[mt], aLo, m0 + 16 * mt, klo, lane);
        }
        uint32_t Bh[2][4], Bl[2][4];
        #pragma unroll
        for (int p = 0; p < 2; p++) {
            ldsmB(Bh[p], bHi, n0 + p * 16, klo, lane);
            ldsmB(Bl[p], bLo, n0 + p * 16, klo, lane);
        }
        #pragma unroll
        for (int mt = 0; mt < 2; mt++) {
            #pragma unroll
            for (int p = 0; p < 2; p++) {
                #pragma unroll
                for (int s = 0; s < 2; s++) {
                    int nt = p * 2 + s;
                    mma16816(acc[mt][nt], Ah[mt], &Bh[p][s * 2]);
                    mma16816(acc[mt][nt], Ah[mt], &Bl[p][s * 2]);
                    mma16816(acc[mt][nt], Al[mt], &Bh[p][s * 2]);
                }
            }
        }
    }
}

// ---------------- fused GEMM-chain message kernel (R14 winner, unchanged) ----------------
template<bool EDGE>
__global__ void __launch_bounds__(NTHR, 2)
gemm_msg_kernel(const __nv_bfloat16* __restrict__ vhi,
                const __nv_bfloat16* __restrict__ vlo,
                const float* __restrict__ hE,
                const void*  __restrict__ Eidx,
                const float* __restrict__ maskA,
                const float* __restrict__ bb, const float* __restrict__ bc,
                int wbase,
                const float* __restrict__ lng, const float* __restrict__ lnb,
                float* __restrict__ out)
{
    extern __shared__ uint8_t smem8[];
    const int tid  = threadIdx.x;
    const int wid  = tid >> 5;
    const int lane = tid & 31;
    const int e0   = blockIdx.x * MT;
    const int is64 = g_idx64;
    const uint32_t sbase = smem_u32(smem8);

    const int m0 = (wid & 1) * 32;
    const int n0 = (wid >> 1) * 32;

    const __nv_bfloat16* WTh = g_WThi + wbase;
    const __nv_bfloat16* WTl = g_WTlo + wbase;

    float acc[2][4][4];
    auto zero_acc = [&]() {
        #pragma unroll
        for (int mt = 0; mt < 2; mt++)
            #pragma unroll
            for (int nt = 0; nt < 4; nt++)
                #pragma unroll
                for (int i = 0; i < 4; i++) acc[mt][nt][i] = 0.f;
    };

    auto fill_B = [&](int woff, int Klen, int kbase, uint32_t reg) {
        const __nv_bfloat16* bh = WTh + woff;
        const __nv_bfloat16* bl = WTl + woff;
        int u = tid & 7;
        #pragma unroll
        for (int n = tid >> 3; n < 128; n += 32) {
            uint32_t sw = sw128((uint32_t)n * 128 + u * 16);
            cp_async16(sbase + reg + sw,          bh + (size_t)n * Klen + kbase + u * 8);
            cp_async16(sbase + reg + TILE_W + sw, bl + (size_t)n * Klen + kbase + u * 8);
        }
    };

    auto fill_A = [&](int ch, int slot) {
        uint32_t aH = sbase + REG2 + slot * TILE_A;
        uint32_t aL = aH + 2 * TILE_A;
        if (ch < 2) {
            uint8_t* pH = smem8 + REG2 + slot * TILE_A;
            uint8_t* pL = pH + 2 * TILE_A;
            int c4 = tid & 15;
            #pragma unroll
            for (int r = tid >> 4; r < MT; r += 16) {
                int e = e0 + r;
                const float* src = hE + (size_t)e * HH + ch * 64;
                float4 v = *((const float4*)src + c4);
                uint32_t h01, l01, h23, l23;
                split2(v.x, v.y, h01, l01);
                split2(v.z, v.w, h23, l23);
                uint32_t sw = sw128((uint32_t)r * 128 + c4 * 8);
                *(uint2*)(pH + sw) = make_uint2(h01, h23);
                *(uint2*)(pL + sw) = make_uint2(l01, l23);
            }
        } else {
            int u = tid & 7;
            #pragma unroll
            for (int r = tid >> 3; r < MT; r += 32) {
                int e = e0 + r;
                int b  = e / (KK * NN);
                int nb = load_nbidx(Eidx, is64, e);
                size_t off = ((size_t)b * NN + nb) * HH + (ch - 2) * 64 + u * 8;
                uint32_t sw = sw128((uint32_t)r * 128 + u * 16);
                cp_async16(aH + sw, vhi + off);
                cp_async16(aL + sw, vlo + off);
            }
        }
    };

    auto epi_act = [&](const float* __restrict__ bias, bool useCW, uint32_t dstReg) {
        #pragma unroll
        for (int mt = 0; mt < 2; mt++) {
            int row = m0 + mt * 16 + (lane >> 2);
            const float* cw0 = nullptr; const float* cw1 = nullptr;
            if (useCW) {
                cw0 = g_cw + (size_t)((e0 + row) / KK) * HH;
                cw1 = g_cw + (size_t)((e0 + row + 8) / KK) * HH;
            }
            #pragma unroll
            for (int nt = 0; nt < 4; nt++) {
                int c0 = n0 + nt * 8 + 2 * (lane & 3);
                float b00, b01, b10, b11;
                if (useCW) { b00 = cw0[c0]; b01 = cw0[c0 + 1]; b10 = cw1[c0]; b11 = cw1[c0 + 1]; }
                else       { b00 = b10 = bias[c0]; b01 = b11 = bias[c0 + 1]; }
                int kc = c0 >> 6, kk = c0 & 63;
                uint8_t* dH = smem8 + dstReg + kc * TILE_A;
                uint8_t* dL = dH + 2 * TILE_A;
                float x0 = gelu_exact(acc[mt][nt][0] + b00);
                float y0 = gelu_exact(acc[mt][nt][1] + b01);
                float x1 = gelu_exact(acc[mt][nt][2] + b10);
                float y1 = gelu_exact(acc[mt][nt][3] + b11);
                uint32_t hi, lo;
                split2(x0, y0, hi, lo);
                uint32_t sw = sw128((uint32_t)(row * 128 + kk * 2));
                *(uint32_t*)(dH + sw) = hi; *(uint32_t*)(dL + sw) = lo;
                split2(x1, y1, hi, lo);
                sw = sw128((uint32_t)((row + 8) * 128 + kk * 2));
                *(uint32_t*)(dH + sw) = hi; *(uint32_t*)(dL + sw) = lo;
            }
        }
    };

    auto mmaA = [&](uint32_t reg, int kc, uint32_t bReg) {
        mma_chunk(sbase + reg + kc * TILE_A, sbase + reg + 2 * TILE_A + kc * TILE_A,
                  sbase + bReg, sbase + bReg + TILE_W, m0, n0, lane, acc);
    };

    // ===== GEMM1: K=256, 4 chunks. A ping-pong in R2, B ping-pong R0/R1 =====
    zero_acc();
    fill_B(WOFF_G1, 384, 128, REG0);
    fill_A(0, 0);
    CP_WAIT_ALL();
    __syncthreads();
    fill_A(1, 1); fill_B(WOFF_G1, 384, 192, REG1);
    mmaA(REG2, 0, REG0);
    CP_WAIT_ALL(); __syncthreads();
    fill_A(2, 0); fill_B(WOFF_G1, 384, 256, REG0);
    mmaA(REG2, 1, REG1);
    CP_WAIT_ALL(); __syncthreads();
    fill_A(3, 1); fill_B(WOFF_G1, 384, 320, REG1);
    mmaA(REG2, 0, REG0);
    CP_WAIT_ALL(); __syncthreads();
    mmaA(REG2, 1, REG1);
    __syncthreads();

    // ===== epilogue1 (+cw) -> R2; B(G2,k0) -> R0 =====
    fill_B(WOFF_G2, 128, 0, REG0);
    epi_act(nullptr, true, REG2);
    zero_acc();
    CP_WAIT_ALL(); __syncthreads();

    // ===== GEMM2: A in R2, B R0 then R1 =====
    fill_B(WOFF_G2, 128, 64, REG1);
    mmaA(REG2, 0, REG0);
    CP_WAIT_ALL(); __syncthreads();
    fill_B(WOFF_G3, 128, 0, REG0);
    mmaA(REG2, 1, REG1);
    CP_WAIT_ALL(); __syncthreads();

    // ===== epilogue2 -> R1; B(G3,k64) -> R2 =====
    fill_B(WOFF_G3, 128, 64, REG2);
    epi_act(bb, false, REG1);
    zero_acc();
    CP_WAIT_ALL(); __syncthreads();

    // ===== GEMM3: A in R1, B R0 then R2 =====
    mmaA(REG1, 0, REG0);
    mmaA(REG1, 1, REG2);
    __syncthreads();

    float* sOut = (float*)(smem8 + REG0);
    {
        #pragma unroll
        for (int mt = 0; mt < 2; mt++) {
            int row = m0 + mt * 16 + (lane >> 2);
            float mk0 = 1.f, mk1 = 1.f;
            if (!EDGE) { mk0 = maskA[e0 + row]; mk1 = maskA[e0 + row + 8]; }
            #pragma unroll
            for (int nt = 0; nt < 4; nt++) {
                int c0 = n0 + nt * 8 + 2 * (lane & 3);
                float b0v = bc[c0], b1v = bc[c0 + 1];
                sOut[row * 128 + c0]           = (acc[mt][nt][0] + b0v) * mk0;
                sOut[row * 128 + c0 + 1]       = (acc[mt][nt][1] + b1v) * mk0;
                sOut[(row + 8) * 128 + c0]     = (acc[mt][nt][2] + b0v) * mk1;
                sOut[(row + 8) * 128 + c0 + 1] = (acc[mt][nt][3] + b1v) * mk1;
            }
        }
        __syncthreads();
    }

    if (!EDGE) {
        float4* d4 = (float4*)(g_m + (size_t)e0 * HH);
        const float4* s4 = (const float4*)sOut;
        #pragma unroll
        for (int p = 0; p < 8; p++) d4[tid + p * NTHR] = s4[tid + p * NTHR];
    } else {
        for (int r = wid; r < MT; r += 8) {
            const float* her = hE + (size_t)(e0 + r) * HH;
            float v[4];
            #pragma unroll
            for (int u = 0; u < 4; u++) {
                int c = lane + 32 * u;
                v[u] = sOut[r * 128 + c] + her[c];
            }
            float s  = v[0] + v[1] + v[2] + v[3];
            float ss = v[0]*v[0] + v[1]*v[1] + v[2]*v[2] + v[3]*v[3];
            #pragma unroll
            for (int o = 16; o; o >>= 1) {
                s  += __shfl_xor_sync(0xffffffffu, s, o);
                ss += __shfl_xor_sync(0xffffffffu, ss, o);
            }
            float mean = s * (1.0f / 128.0f);
            float rstd = rsqrtf(ss * (1.0f / 128.0f) - mean * mean + 1e-5f);
            #pragma unroll
            for (int u = 0; u < 4; u++) {
                int c = lane + 32 * u;
                out[(size_t)(e0 + r) * HH + c] = (v[u] - mean) * rstd * lng[c] + lnb[c];
            }
        }
    }
}

// ---------------- node reduction + LN1 (standalone, 2048 blocks) ----------------
__global__ void __launch_bounds__(128)
reduce_ln1(const float* __restrict__ hV,
           const float* __restrict__ lng, const float* __restrict__ lnb)
{
    int bn = blockIdx.x, j = threadIdx.x;
    int w = j >> 5, lane = j & 31;
    float s = 0.f;
    const float* mp = g_m + (size_t)bn * KK * HH + j;
    #pragma unroll 8
    for (int k = 0; k < KK; k++) s += mp[(size_t)k * HH];
    float v = hV[(size_t)bn * HH + j] + s * (1.0f / 48.0f);

    __shared__ float rs[4], rq[4];
    float a = v, q = v * v;
    #pragma unroll
    for (int o = 16; o; o >>= 1) {
        a += __shfl_xor_sync(0xffffffffu, a, o);
        q += __shfl_xor_sync(0xffffffffu, q, o);
    }
    if (lane == 0) { rs[w] = a; rq[w] = q; }
    __syncthreads();
    float S = rs[0] + rs[1] + rs[2] + rs[3];
    float Q = rq[0] + rq[1] + rq[2] + rq[3];
    float mean = S * (1.0f / 128.0f);
    float rstd = rsqrtf(Q * (1.0f / 128.0f) - mean * mean + 1e-5f);
    g_hV1[(size_t)bn * HH + j] = (v - mean) * rstd * lng[j] + lnb[j];
}

// ---------------- FFN + LN2 + mask_V + h_Vn split + cw2 ----------------
__global__ void __launch_bounds__(256, 1)
ffn_kernel(const float* __restrict__ Win, const float* __restrict__ bin,
           const float* __restrict__ Wout, const float* __restrict__ bout,
           const float* __restrict__ lng, const float* __restrict__ lnb,
           const float* __restrict__ maskV,
           const float* __restrict__ W11, const float* __restrict__ W11b,
           float* __restrict__ out)
{
    __shared__ float sX[16 * 128];
    __shared__ float sH[16 * 512];
    const int tid  = threadIdx.x;
    const int row0 = blockIdx.x * 16;
    const int lane = tid & 31;

    for (int idx = tid; idx < 16 * 128; idx += 256)
        sX[idx] = g_hV1[(size_t)row0 * 128 + idx];
    __syncthreads();

    // ---- hidden ----
    {
        const int j0 = tid * 2;
        float acc[16][2];
        #pragma unroll
        for (int r = 0; r < 16; r++) { acc[r][0] = bin[j0]; acc[r][1] = bin[j0 + 1]; }
        #pragma unroll 2
        for (int i = 0; i < 128; i++) {
            float2 w = *reinterpret_cast<const float2*>(Win + i * FFD + j0);
            #pragma unroll
            for (int r = 0; r < 16; r++) {
                float a = sX[r * 128 + i];
                acc[r][0] = fmaf(a, w.x, acc[r][0]);
                acc[r][1] = fmaf(a, w.y, acc[r][1]);
            }
        }
        #pragma unroll
        for (int r = 0; r < 16; r++) {
            sH[r * FFD + j0]     = gelu_exact(acc[r][0]);
            sH[r * FFD + j0 + 1] = gelu_exact(acc[r][1]);
        }
    }
    __syncthreads();

    // ---- output projection + residual ----
    {
        const int j = tid & 127, rh = tid >> 7;
        float acc[8];
        #pragma unroll
        for (int r = 0; r < 8; r++) acc[r] = bout[j];
        #pragma unroll 2
        for (int i = 0; i < FFD; i++) {
            float w = Wout[i * 128 + j];
            #pragma unroll
            for (int r = 0; r < 8; r++)
                acc[r] = fmaf(sH[(rh * 8 + r) * FFD + i], w, acc[r]);
        }
        #pragma unroll
        for (int r = 0; r < 8; r++)
            sX[(rh * 8 + r) * 128 + j] += acc[r];
    }
    __syncthreads();

    // ---- LN2 + mask -> out + bf16 split; stash h_Vn into sH ----
    {
        int w = tid >> 5;
        for (int r = w; r < 16; r += 8) {
            float v[4];
            #pragma unroll
            for (int u = 0; u < 4; u++) v[u] = sX[r * 128 + lane + 32 * u];
            float s  = v[0] + v[1] + v[2] + v[3];
            float ss = v[0]*v[0] + v[1]*v[1] + v[2]*v[2] + v[3]*v[3];
            #pragma unroll
            for (int o = 16; o; o >>= 1) {
                s  += __shfl_xor_sync(0xffffffffu, s, o);
                ss += __shfl_xor_sync(0xffffffffu, ss, o);
            }
            float mean = s * (1.0f / 128.0f);
            float rstd = rsqrtf(ss * (1.0f / 128.0f) - mean * mean + 1e-5f);
            float mk = maskV[row0 + r];
            #pragma unroll
            for (int u = 0; u < 4; u++) {
                int c = lane + 32 * u;
                float val = mk * ((v[u] - mean) * rstd * lng[c] + lnb[c]);
                size_t gi = ((size_t)row0 + r) * 128 + c;
                out[gi] = val;
                __nv_bfloat16 h = __float2bfloat16(val);
                g_hV2hi[gi] = h;
                g_hV2lo[gi] = __float2bfloat16(val - __bfloat162float(h));
                sH[r * 128 + c] = val;
            }
        }
    }
    __syncthreads();

    // ---- cw2[row][j] = W11b[j] + h_Vn . W11[:128,j] ----
    {
        int g = tid >> 7, j = tid & 127;
        float acc[8];
        #pragma unroll
        for (int r8 = 0; r8 < 8; r8++) acc[r8] = W11b[j];
        #pragma unroll 4
        for (int i = 0; i < 128; i++) {
            float w = W11[i * HH + j];
            #pragma unroll
            for (int r8 = 0; r8 < 8; r8++)
                acc[r8] = fmaf(sH[(g + 2 * r8) * 128 + i], w, acc[r8]);
        }
        #pragma unroll
        for (int r8 = 0; r8 < 8; r8++)
            g_cw[(size_t)(row0 + g + 2 * r8) * HH + j] = acc[r8];
    }
}

extern "C" void kernel_launch(void* const* d_in, const int* in_sizes, int n_in,
                              void* d_out, int out_size)
{
    const float* hV    = (const float*)d_in[0];
    const float* hE    = (const float*)d_in[1];
    const void*  Eidx  = d_in[2];
    const float* maskV = (const float*)d_in[3];
    const float* maskA = (const float*)d_in[4];
    const float* W1w  = (const float*)d_in[5],  *W1b  = (const float*)d_in[6];
    const float* W2w  = (const float*)d_in[7],  *W2b  = (const float*)d_in[8];
    const float* W3w  = (const float*)d_in[9],  *W3b  = (const float*)d_in[10];
    const float* W11w = (const float*)d_in[11], *W11b = (const float*)d_in[12];
    const float* W12w = (const float*)d_in[13], *W12b = (const float*)d_in[14];
    const float* W13w = (const float*)d_in[15], *W13b = (const float*)d_in[16];
    const float* Winw = (const float*)d_in[17], *Winb = (const float*)d_in[18];
    const float* Woutw= (const float*)d_in[19], *Woutb= (const float*)d_in[20];
    const float* ln1g = (const float*)d_in[21], *ln1b = (const float*)d_in[22];
    const float* ln2g = (const float*)d_in[23], *ln2b = (const float*)d_in[24];
    const float* ln3g = (const float*)d_in[25], *ln3b = (const float*)d_in[26];

    float* out_hV = (float*)d_out;
    float* out_hE = out_hV + (size_t)BN * HH;

    cudaFuncSetAttribute(gemm_msg_kernel<false>, cudaFuncAttributeMaxDynamicSharedMemorySize, SM_TOTAL);
    cudaFuncSetAttribute(gemm_msg_kernel<true>,  cudaFuncAttributeMaxDynamicSharedMemorySize, SM_TOTAL);

    __nv_bfloat16 *vhi, *vlo, *v2hi, *v2lo;
    cudaGetSymbolAddress((void**)&vhi,  g_hVhi);
    cudaGetSymbolAddress((void**)&vlo,  g_hVlo);
    cudaGetSymbolAddress((void**)&v2hi, g_hV2hi);
    cudaGetSymbolAddress((void**)&v2lo, g_hV2lo);

    // 1) prep: idx detect + weight transposes + hV split + cw1
    prep_all<<<PW_BLKS + PV_BLKS + PC_BLKS, 256>>>(
        W1w, W2w, W3w, W11w, W12w, W13w, hV, W1b, (const int*)Eidx);
    // 2) node message chain -> g_m
    gemm_msg_kernel<false><<<NCTA, NTHR, SM_TOTAL>>>(
        vhi, vlo, hE, Eidx, maskA, W2b, W3b, 0, nullptr, nullptr, nullptr);
    // 3) LN1 reduction (high-parallelism standalone)
    reduce_ln1<<<BN, 128>>>(hV, ln1g, ln1b);
    // 4) FFN + LN2 + mask + split + cw2
    ffn_kernel<<<BN / 16, 256>>>(Winw, Winb, Woutw, Woutb,
                                 ln2g, ln2b, maskV, W11w, W11b, out_hV);
    // 5) edge message chain + LN3
    gemm_msg_kernel<true><<<NCTA, NTHR, SM_TOTAL>>>(
        v2hi, v2lo, hE, Eidx, maskA, W12b, W13b, WMSG, ln3g, ln3b, out_hE);

    (void)in_sizes; (void)n_in; (void)out_size;
}

// round 17
// speedup vs baseline: 1.2810x; 1.2808x over previous
#include <cuda_runtime.h>
#include <cuda_bf16.h>
#include <cstdint>

#define BB  2
#define NN  1024
#define KK  48
#define HH  128
#define FFD 512
#define BN  (BB*NN)
#define NEDGE (BN*KK)          // 98304
#define MT  64
#define NCTA (NEDGE/MT)        // 1536
#define NTHR 256
#define FROWS 8

// Three 32KB regions rotate roles. Tiles (SW128): B half = 16KB; A tile = 8KB.
#define TILE_W  16384
#define TILE_A  8192
#define REG0 1024
#define REG1 (REG0 + 32768)
#define REG2 (REG1 + 32768)
#define SM_TOTAL (REG2 + 32768)   // 99328 -> 2 CTAs/SM

#define WOFF_G1 0
#define WOFF_G2 (384*HH)
#define WOFF_G3 (WOFF_G2 + 128*HH)
#define WMSG    (WOFF_G3 + 128*HH)

__device__ float g_hV1[BN*HH];
__device__ float g_m[(size_t)NEDGE*HH];
__device__ float g_cw[BN*HH];
__device__ __align__(16) __nv_bfloat16 g_WThi[2*WMSG];
__device__ __align__(16) __nv_bfloat16 g_WTlo[2*WMSG];
__device__ __align__(16) __nv_bfloat16 g_hVhi[BN*HH],  g_hVlo[BN*HH];
__device__ __align__(16) __nv_bfloat16 g_hV2hi[BN*HH], g_hV2lo[BN*HH];
__device__ int g_idx64;

__device__ __forceinline__ float gelu_exact(float x) {
    return 0.5f * x * (1.0f + erff(x * 0.70710678118654752f));
}

__device__ __forceinline__ int load_nbidx(const void* Eidx, int is64, long long pos) {
    int v;
    if (is64) v = (int)((const long long*)Eidx)[pos];
    else      v = ((const int*)Eidx)[pos];
    v = v < 0 ? 0 : (v >= NN ? NN - 1 : v);
    return v;
}

// -------- prep: idx detect + 6 weight transposes + hV split + cw1 --------
#define PW_BLKS 640
#define PV_BLKS 256
#define PC_BLKS (BN/2)
__global__ void __launch_bounds__(256)
prep_all(const float* __restrict__ W1,  const float* __restrict__ W2,
         const float* __restrict__ W3,  const float* __restrict__ W11,
         const float* __restrict__ W12, const float* __restrict__ W13,
         const float* __restrict__ hV,  const float* __restrict__ W1b,
         const int* __restrict__ e32)
{
    __shared__ float sc[256];
    int blk = blockIdx.x, tid = threadIdx.x;
    if (blk == 0 && tid == 0) {
        int all0 = 1;
        #pragma unroll
        for (int i = 1; i < 96; i += 2) all0 &= (e32[i] == 0);
        g_idx64 = all0;
    }
    if (blk < PW_BLKS) {
        int id = blk * 256 + tid;
        const float* src; int base, K;
        if      (id < 49152)  { src = W1;  base = 0;      K = 384; }
        else if (id < 65536)  { src = W2;  base = 49152;  K = 128; }
        else if (id < 81920)  { src = W3;  base = 65536;  K = 128; }
        else if (id < 131072) { src = W11; base = 81920;  K = 384; }
        else if (id < 147456) { src = W12; base = 131072; K = 128; }
        else                  { src = W13; base = 147456; K = 128; }
        int local = id - base;
        int k = local >> 7, n = local & 127;
        float x = src[local];
        __nv_bfloat16 h = __float2bfloat16(x);
        g_WThi[base + (size_t)n * K + k] = h;
        g_WTlo[base + (size_t)n * K + k] = __float2bfloat16(x - __bfloat162float(h));
    } else if (blk < PW_BLKS + PV_BLKS) {
        int idx = (blk - PW_BLKS) * 256 + tid;
        float4 v = ((const float4*)hV)[idx];
        __nv_bfloat16 h0 = __float2bfloat16(v.x), h1 = __float2bfloat16(v.y);
        __nv_bfloat16 h2 = __float2bfloat16(v.z), h3 = __float2bfloat16(v.w);
        __nv_bfloat162* ph = (__nv_bfloat162*)(g_hVhi + (size_t)idx * 4);
        __nv_bfloat162* pl = (__nv_bfloat162*)(g_hVlo + (size_t)idx * 4);
        ph[0] = __nv_bfloat162(h0, h1); ph[1] = __nv_bfloat162(h2, h3);
        pl[0] = __nv_bfloat162(__float2bfloat16(v.x - __bfloat162float(h0)),
                               __float2bfloat16(v.y - __bfloat162float(h1)));
        pl[1] = __nv_bfloat162(__float2bfloat16(v.z - __bfloat162float(h2)),
                               __float2bfloat16(v.w - __bfloat162float(h3)));
    } else {
        int g = tid >> 7, j = tid & 127;
        int bn = (blk - PW_BLKS - PV_BLKS) * 2 + g;
        sc[g * 128 + j] = hV[(size_t)bn * HH + j];
        __syncthreads();
        float acc = W1b[j];
        const float* base = sc + g * 128;
        #pragma unroll 8
        for (int i = 0; i < 128; i++) acc = fmaf(base[i], W1[i * HH + j], acc);
        g_cw[(size_t)bn * HH + j] = acc;
    }
}

// ---------------- PTX helpers ----------------
__device__ __forceinline__ uint32_t smem_u32(const void* p) {
    uint32_t a;
    asm("{ .reg .u64 t; cvta.to.shared.u64 t, %1; cvt.u32.u64 %0, t; }" : "=r"(a) : "l"(p));
    return a;
}
__device__ __forceinline__ uint32_t sw128(uint32_t off) {
    return off ^ ((off >> 3) & 0x70);
}
__device__ __forceinline__ void cp_async16(uint32_t dst, const void* src) {
    asm volatile("cp.async.cg.shared.global [%0], [%1], 16;" :: "r"(dst), "l"(src));
}
#define CP_WAIT_ALL() asm volatile("cp.async.wait_all;" ::: "memory")
__device__ __forceinline__ void ldsm4(uint32_t* r, uint32_t addr) {
    asm volatile("ldmatrix.sync.aligned.m8n8.x4.shared.b16 {%0,%1,%2,%3}, [%4];"
        : "=r"(r[0]), "=r"(r[1]), "=r"(r[2]), "=r"(r[3]) : "r"(addr));
}
__device__ __forceinline__ void mma16816(float* d, const uint32_t* a, const uint32_t* b) {
    asm volatile("mma.sync.aligned.m16n8k16.row.col.f32.bf16.bf16.f32 "
        "{%0,%1,%2,%3}, {%4,%5,%6,%7}, {%8,%9}, {%0,%1,%2,%3};"
        : "+f"(d[0]), "+f"(d[1]), "+f"(d[2]), "+f"(d[3])
        : "r"(a[0]), "r"(a[1]), "r"(a[2]), "r"(a[3]), "r"(b[0]), "r"(b[1]));
}
__device__ __forceinline__ void ldsmA(uint32_t* r, uint32_t tbase, int mrow, int klo, int lane) {
    int q = lane >> 3;
    int row = mrow + (lane & 7) + 8 * (q & 1);
    int kk  = klo + 8 * (q >> 1);
    ldsm4(r, tbase + sw128((uint32_t)(row * 128 + kk * 2)));
}
__device__ __forceinline__ void ldsmB(uint32_t* r, uint32_t tbase, int nrow0, int klo, int lane) {
    int q = lane >> 3;
    int row = nrow0 + (lane & 7) + 8 * (q >> 1);
    int kk  = klo + 8 * (q & 1);
    ldsm4(r, tbase + sw128((uint32_t)(row * 128 + kk * 2)));
}
__device__ __forceinline__ uint32_t pack_bf2(__nv_bfloat16 a, __nv_bfloat16 b) {
    return (uint32_t)__bfloat16_as_ushort(a) | ((uint32_t)__bfloat16_as_ushort(b) << 16);
}
__device__ __forceinline__ void split2(float x, float y, uint32_t& hi, uint32_t& lo) {
    __nv_bfloat16 hx = __float2bfloat16(x), hy = __float2bfloat16(y);
    __nv_bfloat16 lx = __float2bfloat16(x - __bfloat162float(hx));
    __nv_bfloat16 ly = __float2bfloat16(y - __bfloat162float(hy));
    hi = pack_bf2(hx, hy);
    lo = pack_bf2(lx, ly);
}

// warp tile 32(m) x 32(n): acc[2][4][4]; per k16: 8 LDSM vs 24 HMMA
__device__ __forceinline__ void mma_chunk(uint32_t aHi, uint32_t aLo,
                                          uint32_t bHi, uint32_t bLo,
                                          int m0, int n0, int lane,
                                          float acc[2][4][4]) {
    #pragma unroll
    for (int ks = 0; ks < 4; ks++) {
        int klo = ks * 16;
        uint32_t Ah[2][4], Al[2][4];
        #pragma unroll
        for (int mt = 0; mt < 2; mt++) {
            ldsmA(Ah[mt], aHi, m0 + 16 * mt, klo, lane);
            ldsmA(Al[mt], aLo, m0 + 16 * mt, klo, lane);
        }
        uint32_t Bh[2][4], Bl[2][4];
        #pragma unroll
        for (int p = 0; p < 2; p++) {
            ldsmB(Bh[p], bHi, n0 + p * 16, klo, lane);
            ldsmB(Bl[p], bLo, n0 + p * 16, klo, lane);
        }
        #pragma unroll
        for (int mt = 0; mt < 2; mt++) {
            #pragma unroll
            for (int p = 0; p < 2; p++) {
                #pragma unroll
                for (int s = 0; s < 2; s++) {
                    int nt = p * 2 + s;
                    mma16816(acc[mt][nt], Ah[mt], &Bh[p][s * 2]);
                    mma16816(acc[mt][nt], Ah[mt], &Bl[p][s * 2]);
                    mma16816(acc[mt][nt], Al[mt], &Bh[p][s * 2]);
                }
            }
        }
    }
}

// ---------------- fused GEMM-chain message kernel (R14 winner, unchanged) ----------------
template<bool EDGE>
__global__ void __launch_bounds__(NTHR, 2)
gemm_msg_kernel(const __nv_bfloat16* __restrict__ vhi,
                const __nv_bfloat16* __restrict__ vlo,
                const float* __restrict__ hE,
                const void*  __restrict__ Eidx,
                const float* __restrict__ maskA,
                const float* __restrict__ bb, const float* __restrict__ bc,
                int wbase,
                const float* __restrict__ lng, const float* __restrict__ lnb,
                float* __restrict__ out)
{
    extern __shared__ uint8_t smem8[];
    const int tid  = threadIdx.x;
    const int wid  = tid >> 5;
    const int lane = tid & 31;
    const int e0   = blockIdx.x * MT;
    const int is64 = g_idx64;
    const uint32_t sbase = smem_u32(smem8);

    const int m0 = (wid & 1) * 32;
    const int n0 = (wid >> 1) * 32;

    const __nv_bfloat16* WTh = g_WThi + wbase;
    const __nv_bfloat16* WTl = g_WTlo + wbase;

    float acc[2][4][4];
    auto zero_acc = [&]() {
        #pragma unroll
        for (int mt = 0; mt < 2; mt++)
            #pragma unroll
            for (int nt = 0; nt < 4; nt++)
                #pragma unroll
                for (int i = 0; i < 4; i++) acc[mt][nt][i] = 0.f;
    };

    auto fill_B = [&](int woff, int Klen, int kbase, uint32_t reg) {
        const __nv_bfloat16* bh = WTh + woff;
        const __nv_bfloat16* bl = WTl + woff;
        int u = tid & 7;
        #pragma unroll
        for (int n = tid >> 3; n < 128; n += 32) {
            uint32_t sw = sw128((uint32_t)n * 128 + u * 16);
            cp_async16(sbase + reg + sw,          bh + (size_t)n * Klen + kbase + u * 8);
            cp_async16(sbase + reg + TILE_W + sw, bl + (size_t)n * Klen + kbase + u * 8);
        }
    };

    auto fill_A = [&](int ch, int slot) {
        uint32_t aH = sbase + REG2 + slot * TILE_A;
        uint32_t aL = aH + 2 * TILE_A;
        if (ch < 2) {
            uint8_t* pH = smem8 + REG2 + slot * TILE_A;
            uint8_t* pL = pH + 2 * TILE_A;
            int c4 = tid & 15;
            #pragma unroll
            for (int r = tid >> 4; r < MT; r += 16) {
                int e = e0 + r;
                const float* src = hE + (size_t)e * HH + ch * 64;
                float4 v = *((const float4*)src + c4);
                uint32_t h01, l01, h23, l23;
                split2(v.x, v.y, h01, l01);
                split2(v.z, v.w, h23, l23);
                uint32_t sw = sw128((uint32_t)r * 128 + c4 * 8);
                *(uint2*)(pH + sw) = make_uint2(h01, h23);
                *(uint2*)(pL + sw) = make_uint2(l01, l23);
            }
        } else {
            int u = tid & 7;
            #pragma unroll
            for (int r = tid >> 3; r < MT; r += 32) {
                int e = e0 + r;
                int b  = e / (KK * NN);
                int nb = load_nbidx(Eidx, is64, e);
                size_t off = ((size_t)b * NN + nb) * HH + (ch - 2) * 64 + u * 8;
                uint32_t sw = sw128((uint32_t)r * 128 + u * 16);
                cp_async16(aH + sw, vhi + off);
                cp_async16(aL + sw, vlo + off);
            }
        }
    };

    auto epi_act = [&](const float* __restrict__ bias, bool useCW, uint32_t dstReg) {
        #pragma unroll
        for (int mt = 0; mt < 2; mt++) {
            int row = m0 + mt * 16 + (lane >> 2);
            const float* cw0 = nullptr; const float* cw1 = nullptr;
            if (useCW) {
                cw0 = g_cw + (size_t)((e0 + row) / KK) * HH;
                cw1 = g_cw + (size_t)((e0 + row + 8) / KK) * HH;
            }
            #pragma unroll
            for (int nt = 0; nt < 4; nt++) {
                int c0 = n0 + nt * 8 + 2 * (lane & 3);
                float b00, b01, b10, b11;
                if (useCW) { b00 = cw0[c0]; b01 = cw0[c0 + 1]; b10 = cw1[c0]; b11 = cw1[c0 + 1]; }
                else       { b00 = b10 = bias[c0]; b01 = b11 = bias[c0 + 1]; }
                int kc = c0 >> 6, kk = c0 & 63;
                uint8_t* dH = smem8 + dstReg + kc * TILE_A;
                uint8_t* dL = dH + 2 * TILE_A;
                float x0 = gelu_exact(acc[mt][nt][0] + b00);
                float y0 = gelu_exact(acc[mt][nt][1] + b01);
                float x1 = gelu_exact(acc[mt][nt][2] + b10);
                float y1 = gelu_exact(acc[mt][nt][3] + b11);
                uint32_t hi, lo;
                split2(x0, y0, hi, lo);
                uint32_t sw = sw128((uint32_t)(row * 128 + kk * 2));
                *(uint32_t*)(dH + sw) = hi; *(uint32_t*)(dL + sw) = lo;
                split2(x1, y1, hi, lo);
                sw = sw128((uint32_t)((row + 8) * 128 + kk * 2));
                *(uint32_t*)(dH + sw) = hi; *(uint32_t*)(dL + sw) = lo;
            }
        }
    };

    auto mmaA = [&](uint32_t reg, int kc, uint32_t bReg) {
        mma_chunk(sbase + reg + kc * TILE_A, sbase + reg + 2 * TILE_A + kc * TILE_A,
                  sbase + bReg, sbase + bReg + TILE_W, m0, n0, lane, acc);
    };

    // ===== GEMM1: K=256, 4 chunks. A ping-pong in R2, B ping-pong R0/R1 =====
    zero_acc();
    fill_B(WOFF_G1, 384, 128, REG0);
    fill_A(0, 0);
    CP_WAIT_ALL();
    __syncthreads();
    fill_A(1, 1); fill_B(WOFF_G1, 384, 192, REG1);
    mmaA(REG2, 0, REG0);
    CP_WAIT_ALL(); __syncthreads();
    fill_A(2, 0); fill_B(WOFF_G1, 384, 256, REG0);
    mmaA(REG2, 1, REG1);
    CP_WAIT_ALL(); __syncthreads();
    fill_A(3, 1); fill_B(WOFF_G1, 384, 320, REG1);
    mmaA(REG2, 0, REG0);
    CP_WAIT_ALL(); __syncthreads();
    mmaA(REG2, 1, REG1);
    __syncthreads();

    // ===== epilogue1 (+cw) -> R2; B(G2,k0) -> R0 =====
    fill_B(WOFF_G2, 128, 0, REG0);
    epi_act(nullptr, true, REG2);
    zero_acc();
    CP_WAIT_ALL(); __syncthreads();

    // ===== GEMM2: A in R2, B R0 then R1 =====
    fill_B(WOFF_G2, 128, 64, REG1);
    mmaA(REG2, 0, REG0);
    CP_WAIT_ALL(); __syncthreads();
    fill_B(WOFF_G3, 128, 0, REG0);
    mmaA(REG2, 1, REG1);
    CP_WAIT_ALL(); __syncthreads();

    // ===== epilogue2 -> R1; B(G3,k64) -> R2 =====
    fill_B(WOFF_G3, 128, 64, REG2);
    epi_act(bb, false, REG1);
    zero_acc();
    CP_WAIT_ALL(); __syncthreads();

    // ===== GEMM3: A in R1, B R0 then R2 =====
    mmaA(REG1, 0, REG0);
    mmaA(REG1, 1, REG2);
    __syncthreads();

    float* sOut = (float*)(smem8 + REG0);
    {
        #pragma unroll
        for (int mt = 0; mt < 2; mt++) {
            int row = m0 + mt * 16 + (lane >> 2);
            float mk0 = 1.f, mk1 = 1.f;
            if (!EDGE) { mk0 = maskA[e0 + row]; mk1 = maskA[e0 + row + 8]; }
            #pragma unroll
            for (int nt = 0; nt < 4; nt++) {
                int c0 = n0 + nt * 8 + 2 * (lane & 3);
                float b0v = bc[c0], b1v = bc[c0 + 1];
                sOut[row * 128 + c0]           = (acc[mt][nt][0] + b0v) * mk0;
                sOut[row * 128 + c0 + 1]       = (acc[mt][nt][1] + b1v) * mk0;
                sOut[(row + 8) * 128 + c0]     = (acc[mt][nt][2] + b0v) * mk1;
                sOut[(row + 8) * 128 + c0 + 1] = (acc[mt][nt][3] + b1v) * mk1;
            }
        }
        __syncthreads();
    }

    if (!EDGE) {
        float4* d4 = (float4*)(g_m + (size_t)e0 * HH);
        const float4* s4 = (const float4*)sOut;
        #pragma unroll
        for (int p = 0; p < 8; p++) d4[tid + p * NTHR] = s4[tid + p * NTHR];
    } else {
        for (int r = wid; r < MT; r += 8) {
            const float* her = hE + (size_t)(e0 + r) * HH;
            float v[4];
            #pragma unroll
            for (int u = 0; u < 4; u++) {
                int c = lane + 32 * u;
                v[u] = sOut[r * 128 + c] + her[c];
            }
            float s  = v[0] + v[1] + v[2] + v[3];
            float ss = v[0]*v[0] + v[1]*v[1] + v[2]*v[2] + v[3]*v[3];
            #pragma unroll
            for (int o = 16; o; o >>= 1) {
                s  += __shfl_xor_sync(0xffffffffu, s, o);
                ss += __shfl_xor_sync(0xffffffffu, ss, o);
            }
            float mean = s * (1.0f / 128.0f);
            float rstd = rsqrtf(ss * (1.0f / 128.0f) - mean * mean + 1e-5f);
            #pragma unroll
            for (int u = 0; u < 4; u++) {
                int c = lane + 32 * u;
                out[(size_t)(e0 + r) * HH + c] = (v[u] - mean) * rstd * lng[c] + lnb[c];
            }
        }
    }
}

// ---------------- node reduction + LN1 (standalone, 2048 blocks) ----------------
__global__ void __launch_bounds__(128)
reduce_ln1(const float* __restrict__ hV,
           const float* __restrict__ lng, const float* __restrict__ lnb)
{
    int bn = blockIdx.x, j = threadIdx.x;
    int w = j >> 5, lane = j & 31;
    float s = 0.f;
    const float* mp = g_m + (size_t)bn * KK * HH + j;
    #pragma unroll 8
    for (int k = 0; k < KK; k++) s += mp[(size_t)k * HH];
    float v = hV[(size_t)bn * HH + j] + s * (1.0f / 48.0f);

    __shared__ float rs[4], rq[4];
    float a = v, q = v * v;
    #pragma unroll
    for (int o = 16; o; o >>= 1) {
        a += __shfl_xor_sync(0xffffffffu, a, o);
        q += __shfl_xor_sync(0xffffffffu, q, o);
    }
    if (lane == 0) { rs[w] = a; rq[w] = q; }
    __syncthreads();
    float S = rs[0] + rs[1] + rs[2] + rs[3];
    float Q = rq[0] + rq[1] + rq[2] + rq[3];
    float mean = S * (1.0f / 128.0f);
    float rstd = rsqrtf(Q * (1.0f / 128.0f) - mean * mean + 1e-5f);
    g_hV1[(size_t)bn * HH + j] = (v - mean) * rstd * lng[j] + lnb[j];
}

// ---------------- FFN + LN2 + mask_V + h_Vn split + cw2 (8 rows/CTA, 256 CTAs) ----------------
__global__ void __launch_bounds__(256, 1)
ffn_kernel(const float* __restrict__ Win, const float* __restrict__ bin,
           const float* __restrict__ Wout, const float* __restrict__ bout,
           const float* __restrict__ lng, const float* __restrict__ lnb,
           const float* __restrict__ maskV,
           const float* __restrict__ W11, const float* __restrict__ W11b,
           float* __restrict__ out)
{
    __shared__ float sX[FROWS * 128];
    __shared__ float sH[FROWS * FFD];
    const int tid  = threadIdx.x;
    const int row0 = blockIdx.x * FROWS;
    const int lane = tid & 31;

    for (int idx = tid; idx < FROWS * 128; idx += 256)
        sX[idx] = g_hV1[(size_t)row0 * 128 + idx];
    __syncthreads();

    // ---- hidden: each thread 2 adjacent cols, 8 rows ----
    {
        const int j0 = tid * 2;
        float acc[FROWS][2];
        #pragma unroll
        for (int r = 0; r < FROWS; r++) { acc[r][0] = bin[j0]; acc[r][1] = bin[j0 + 1]; }
        #pragma unroll 8
        for (int i = 0; i < 128; i++) {
            float2 w = *reinterpret_cast<const float2*>(Win + i * FFD + j0);
            #pragma unroll
            for (int r = 0; r < FROWS; r++) {
                float a = sX[r * 128 + i];
                acc[r][0] = fmaf(a, w.x, acc[r][0]);
                acc[r][1] = fmaf(a, w.y, acc[r][1]);
            }
        }
        #pragma unroll
        for (int r = 0; r < FROWS; r++) {
            sH[r * FFD + j0]     = gelu_exact(acc[r][0]);
            sH[r * FFD + j0 + 1] = gelu_exact(acc[r][1]);
        }
    }
    __syncthreads();

    // ---- output projection + residual: 2 groups x 4 rows ----
    {
        const int j = tid & 127, rh = tid >> 7;
        float acc[4];
        #pragma unroll
        for (int r = 0; r < 4; r++) acc[r] = bout[j];
        #pragma unroll 8
        for (int i = 0; i < FFD; i++) {
            float w = Wout[i * 128 + j];
            #pragma unroll
            for (int r = 0; r < 4; r++)
                acc[r] = fmaf(sH[(rh * 4 + r) * FFD + i], w, acc[r]);
        }
        #pragma unroll
        for (int r = 0; r < 4; r++)
            sX[(rh * 4 + r) * 128 + j] += acc[r];
    }
    __syncthreads();

    // ---- LN2 + mask -> out + bf16 split; stash h_Vn into sH (1 row per warp) ----
    {
        int r = tid >> 5;
        float v[4];
        #pragma unroll
        for (int u = 0; u < 4; u++) v[u] = sX[r * 128 + lane + 32 * u];
        float s  = v[0] + v[1] + v[2] + v[3];
        float ss = v[0]*v[0] + v[1]*v[1] + v[2]*v[2] + v[3]*v[3];
        #pragma unroll
        for (int o = 16; o; o >>= 1) {
            s  += __shfl_xor_sync(0xffffffffu, s, o);
            ss += __shfl_xor_sync(0xffffffffu, ss, o);
        }
        float mean = s * (1.0f / 128.0f);
        float rstd = rsqrtf(ss * (1.0f / 128.0f) - mean * mean + 1e-5f);
        float mk = maskV[row0 + r];
        #pragma unroll
        for (int u = 0; u < 4; u++) {
            int c = lane + 32 * u;
            float val = mk * ((v[u] - mean) * rstd * lng[c] + lnb[c]);
            size_t gi = ((size_t)row0 + r) * 128 + c;
            out[gi] = val;
            __nv_bfloat16 h = __float2bfloat16(val);
            g_hV2hi[gi] = h;
            g_hV2lo[gi] = __float2bfloat16(val - __bfloat162float(h));
            sH[r * 128 + c] = val;
        }
    }
    __syncthreads();

    // ---- cw2: 2 groups; rows {g, g+2, g+4, g+6} ----
    {
        int g = tid >> 7, j = tid & 127;
        float acc[4];
        #pragma unroll
        for (int r4 = 0; r4 < 4; r4++) acc[r4] = W11b[j];
        #pragma unroll 8
        for (int i = 0; i < 128; i++) {
            float w = W11[i * HH + j];
            #pragma unroll
            for (int r4 = 0; r4 < 4; r4++)
                acc[r4] = fmaf(sH[(g + 2 * r4) * 128 + i], w, acc[r4]);
        }
        #pragma unroll
        for (int r4 = 0; r4 < 4; r4++)
            g_cw[(size_t)(row0 + g + 2 * r4) * HH + j] = acc[r4];
    }
}

extern "C" void kernel_launch(void* const* d_in, const int* in_sizes, int n_in,
                              void* d_out, int out_size)
{
    const float* hV    = (const float*)d_in[0];
    const float* hE    = (const float*)d_in[1];
    const void*  Eidx  = d_in[2];
    const float* maskV = (const float*)d_in[3];
    const float* maskA = (const float*)d_in[4];
    const float* W1w  = (const float*)d_in[5],  *W1b  = (const float*)d_in[6];
    const float* W2w  = (const float*)d_in[7],  *W2b  = (const float*)d_in[8];
    const float* W3w  = (const float*)d_in[9],  *W3b  = (const float*)d_in[10];
    const float* W11w = (const float*)d_in[11], *W11b = (const float*)d_in[12];
    const float* W12w = (const float*)d_in[13], *W12b = (const float*)d_in[14];
    const float* W13w = (const float*)d_in[15], *W13b = (const float*)d_in[16];
    const float* Winw = (const float*)d_in[17], *Winb = (const float*)d_in[18];
    const float* Woutw= (const float*)d_in[19], *Woutb= (const float*)d_in[20];
    const float* ln1g = (const float*)d_in[21], *ln1b = (const float*)d_in[22];
    const float* ln2g = (const float*)d_in[23], *ln2b = (const float*)d_in[24];
    const float* ln3g = (const float*)d_in[25], *ln3b = (const float*)d_in[26];

    float* out_hV = (float*)d_out;
    float* out_hE = out_hV + (size_t)BN * HH;

    cudaFuncSetAttribute(gemm_msg_kernel<false>, cudaFuncAttributeMaxDynamicSharedMemorySize, SM_TOTAL);
    cudaFuncSetAttribute(gemm_msg_kernel<true>,  cudaFuncAttributeMaxDynamicSharedMemorySize, SM_TOTAL);

    __nv_bfloat16 *vhi, *vlo, *v2hi, *v2lo;
    cudaGetSymbolAddress((void**)&vhi,  g_hVhi);
    cudaGetSymbolAddress((void**)&vlo,  g_hVlo);
    cudaGetSymbolAddress((void**)&v2hi, g_hV2hi);
    cudaGetSymbolAddress((void**)&v2lo, g_hV2lo);

    // 1) prep: idx detect + weight transposes + hV split + cw1
    prep_all<<<PW_BLKS + PV_BLKS + PC_BLKS, 256>>>(
        W1w, W2w, W3w, W11w, W12w, W13w, hV, W1b, (const int*)Eidx);
    // 2) node message chain -> g_m
    gemm_msg_kernel<false><<<NCTA, NTHR, SM_TOTAL>>>(
        vhi, vlo, hE, Eidx, maskA, W2b, W3b, 0, nullptr, nullptr, nullptr);
    // 3) LN1 reduction
    reduce_ln1<<<BN, 128>>>(hV, ln1g, ln1b);
    // 4) FFN + LN2 + mask + split + cw2 (256 CTAs, 8 rows each)
    ffn_kernel<<<BN / FROWS, 256>>>(Winw, Winb, Woutw, Woutb,
                                    ln2g, ln2b, maskV, W11w, W11b, out_hV);
    // 5) edge message chain + LN3
    gemm_msg_kernel<true><<<NCTA, NTHR, SM_TOTAL>>>(
        v2hi, v2lo, hE, Eidx, maskA, W12b, W13b, WMSG, ln3g, ln3b, out_hE);

    (void)in_sizes; (void)n_in; (void)out_size;
}